// round 16
// baseline (speedup 1.0000x reference)
#include <cuda_runtime.h>
#include <cuda_fp16.h>

#define HID 64
#define MAX_NODES 100000
#define ST 36              // row stride in uints (ldmatrix conflict-free)
#define NODE_SMEM ((3 * 2048 + 128 * 36 + 128) * 4)
// edge smem: sW2[64] + sBf[1024] + 4 warps x (sD+sPQ)[2*32*ST]
#define EDGE_SMEM ((64 + 1024 + 4 * 2 * 32 * ST) * 4)

typedef unsigned int uint;

__device__ __half g_Hh[MAX_NODES * HID];
__device__ __half g_Ph[MAX_NODES * HID];
__device__ __half g_Qh[MAX_NODES * HID];
__device__ int    g_is64;

__device__ __forceinline__ void mma_f16(float4& d, const uint* a, uint b0, uint b1) {
    asm volatile(
        "mma.sync.aligned.m16n8k16.row.col.f32.f16.f16.f32 "
        "{%0,%1,%2,%3}, {%4,%5,%6,%7}, {%8,%9}, {%0,%1,%2,%3};"
        : "+f"(d.x), "+f"(d.y), "+f"(d.z), "+f"(d.w)
        : "r"(a[0]), "r"(a[1]), "r"(a[2]), "r"(a[3]), "r"(b0), "r"(b1));
}
__device__ __forceinline__ void ldm_x4(uint a[4], uint saddr) {
    asm volatile(
        "ldmatrix.sync.aligned.m8n8.x4.shared.b16 {%0,%1,%2,%3}, [%4];"
        : "=r"(a[0]), "=r"(a[1]), "=r"(a[2]), "=r"(a[3]) : "r"(saddr));
}
__device__ __forceinline__ uint smem_u32(const void* p) {
    return (uint)__cvta_generic_to_shared(p);
}

// ---------------------------------------------------------------------------
// Node kernel (v13 structure): per 128-node tile, per-warp 16-row slices.
// Block 0 detects int64-vs-int32 pairs.
// ---------------------------------------------------------------------------
__global__ __launch_bounds__(256, 2) void node_kernel(
        const float* __restrict__ X,
        const float* __restrict__ W1, const float* __restrict__ b1,
        const float* __restrict__ W2, const float* __restrict__ b2,
        const float* __restrict__ We1, const float* __restrict__ be1,
        int n_nodes,
        const int* __restrict__ pairs_w, int n_edges) {
    extern __shared__ uint nsm[];
    uint*  sFr   = nsm;                     // [3][2048] frag-major W2, A, B
    uint*  sh    = nsm + 3 * 2048;          // [128][36] fp16 tile
    float* sbias = (float*)(nsm + 3 * 2048 + 128 * 36);

    int tid = threadIdx.x;

    if (blockIdx.x == 0) {
        int nz = 0;
        long long idx = 1 + 2 * ((long long)tid * (n_edges - 1) / 256);
        if (idx < 2LL * n_edges) nz = pairs_w[idx];
        int any = __syncthreads_or(nz);
        if (tid == 0) g_is64 = (any == 0) ? 1 : 0;
    }

    for (int idx = tid; idx < 3 * 2048; idx += 256) {
        int arr = idx >> 11;
        int id  = idx & 2047;
        int which = id & 1;
        int ln    = (id >> 1) & 31;
        int nt    = (id >> 6) & 7;
        int kt    = id >> 9;
        int cc = ln & 3;
        int rr = ln >> 2;
        int k0 = 16 * kt + (which ? 8 : 0) + 2 * cc;
        int n  = 8 * nt + rr;
        const float* W = (arr == 0) ? W2 : (We1 + (size_t)(arr - 1) * 4096);
        __half2 h = __floats2half2_rn(W[k0 * HID + n], W[(k0 + 1) * HID + n]);
        sFr[idx] = *(uint*)&h;
    }
    if (tid < 64)  sbias[tid] = b2[tid];
    else if (tid < 128) sbias[tid] = be1[tid - 64];

    int q = tid & 15;
    int g = tid >> 4;
    int lane = tid & 31;
    int w    = tid >> 5;
    int c = lane & 3;
    int r = lane >> 2;

    float w1r[4][4];
    #pragma unroll
    for (int cc = 0; cc < 4; cc++) {
        float4 wv = *(const float4*)&W1[cc * HID + 4 * q];
        w1r[cc][0] = wv.x; w1r[cc][1] = wv.y; w1r[cc][2] = wv.z; w1r[cc][3] = wv.w;
    }
    float4 b1r = *(const float4*)&b1[4 * q];

    uint* sW2f = sFr;
    uint* sAf  = sFr + 2048;
    uint* sBf  = sFr + 4096;
    uint shbase = smem_u32(sh);
    uint aaddr0 = shbase + (((16 * w + (lane & 15)) * ST + 4 * (lane >> 4)) << 2);
    __syncthreads();

    for (int tb = blockIdx.x * 128; tb < n_nodes; tb += gridDim.x * 128) {
        #pragma unroll
        for (int i = 0; i < 8; i++) {
            int node = tb + 8 * g + i;
            float4 x = (node < n_nodes) ? *(const float4*)&X[(size_t)node * 4]
                                        : make_float4(0.f, 0.f, 0.f, 0.f);
            float h[4];
            #pragma unroll
            for (int m = 0; m < 4; m++) {
                float hh = ((const float*)&b1r)[m];
                hh = fmaf(x.x, w1r[0][m], hh);
                hh = fmaf(x.y, w1r[1][m], hh);
                hh = fmaf(x.z, w1r[2][m], hh);
                hh = fmaf(x.w, w1r[3][m], hh);
                h[m] = fmaxf(hh, 0.f);
            }
            __half2 h01 = __floats2half2_rn(h[0], h[1]);
            __half2 h23 = __floats2half2_rn(h[2], h[3]);
            *(uint2*)&sh[(8 * g + i) * ST + 2 * q] =
                make_uint2(*(uint*)&h01, *(uint*)&h23);
        }
        __syncwarp();

        {
            float4 acc[8];
            #pragma unroll
            for (int nt = 0; nt < 8; nt++) acc[nt] = make_float4(0.f, 0.f, 0.f, 0.f);
            #pragma unroll
            for (int kt = 0; kt < 4; kt++) {
                uint a[4];
                ldm_x4(a, aaddr0 + kt * 32);
                #pragma unroll
                for (int nt = 0; nt < 8; nt++) {
                    uint2 b = *(const uint2*)&sW2f[((kt * 8 + nt) * 32 + lane) * 2];
                    mma_f16(acc[nt], a, b.x, b.y);
                }
            }
            __syncwarp();
            #pragma unroll
            for (int nt = 0; nt < 8; nt++) {
                float2 bv = *(const float2*)&sbias[8 * nt + 2 * c];
                __half2 lo = __floats2half2_rn(fmaxf(acc[nt].x + bv.x, 0.f),
                                               fmaxf(acc[nt].y + bv.y, 0.f));
                __half2 hi = __floats2half2_rn(fmaxf(acc[nt].z + bv.x, 0.f),
                                               fmaxf(acc[nt].w + bv.y, 0.f));
                sh[(16 * w + r) * ST + 4 * nt + c]     = *(uint*)&lo;
                sh[(16 * w + 8 + r) * ST + 4 * nt + c] = *(uint*)&hi;
            }
        }
        __syncwarp();

        {
            float4 pA[8], qA[8];
            #pragma unroll
            for (int nt = 0; nt < 8; nt++) {
                pA[nt] = make_float4(0.f, 0.f, 0.f, 0.f);
                qA[nt] = make_float4(0.f, 0.f, 0.f, 0.f);
            }
            #pragma unroll
            for (int kt = 0; kt < 4; kt++) {
                uint a[4];
                ldm_x4(a, aaddr0 + kt * 32);
                #pragma unroll
                for (int nt = 0; nt < 8; nt++) {
                    uint2 ba = *(const uint2*)&sAf[((kt * 8 + nt) * 32 + lane) * 2];
                    uint2 bb = *(const uint2*)&sBf[((kt * 8 + nt) * 32 + lane) * 2];
                    mma_f16(pA[nt], a, ba.x, ba.y);
                    mma_f16(qA[nt], a, bb.x, bb.y);
                }
            }
            int nodeLo = tb + 16 * w + r;
            int nodeHi = nodeLo + 8;
            #pragma unroll
            for (int nt = 0; nt < 8; nt++) {
                float2 be = *(const float2*)&sbias[64 + 8 * nt + 2 * c];
                if (nodeLo < n_nodes) {
                    __half2 p = __floats2half2_rn(pA[nt].x + be.x, pA[nt].y + be.y);
                    __half2 qq = __floats2half2_rn(qA[nt].x, qA[nt].y);
                    *(uint*)&g_Ph[(size_t)nodeLo * HID + 8 * nt + 2 * c] = *(uint*)&p;
                    *(uint*)&g_Qh[(size_t)nodeLo * HID + 8 * nt + 2 * c] = *(uint*)&qq;
                }
                if (nodeHi < n_nodes) {
                    __half2 p = __floats2half2_rn(pA[nt].z + be.x, pA[nt].w + be.y);
                    __half2 qq = __floats2half2_rn(qA[nt].z, qA[nt].w);
                    *(uint*)&g_Ph[(size_t)nodeHi * HID + 8 * nt + 2 * c] = *(uint*)&p;
                    *(uint*)&g_Qh[(size_t)nodeHi * HID + 8 * nt + 2 * c] = *(uint*)&qq;
                }
            }
        }

        #pragma unroll
        for (int it = 0; it < 4; it++) {
            int id2 = it * 32 + lane;
            int row = id2 >> 3, ch = id2 & 7;
            int node = tb + 16 * w + row;
            if (node < n_nodes)
                *(uint4*)&g_Hh[(size_t)node * HID + ch * 8] =
                    *(const uint4*)&sh[(16 * w + row) * ST + ch * 4];
        }
        __syncwarp();
    }
}

// ---------------------------------------------------------------------------
// Edge kernel v16: hybrid B-frags (kt 0-1 in regs, kt 2-3 in block smem)
// to cut reg pressure -> 5 blocks/SM. Otherwise identical to v14.
// ---------------------------------------------------------------------------
__global__ __launch_bounds__(128, 5) void edge_kernel(
        const int* __restrict__ pairs,
        const float* __restrict__ We1,
        const float* __restrict__ We2,
        const float* __restrict__ be2,
        float* __restrict__ out,
        int n_edges) {
    extern __shared__ uint es16[];
    float* sW2 = (float*)es16;               // [64]
    uint*  sBf = es16 + 64;                  // [2kt][8nt][32lane][2] (kt 2-3)
    uint*  sDall = es16 + 64 + 1024;

    int tid  = threadIdx.x;
    int lane = tid & 31;
    int wid  = tid >> 5;
    uint* sD  = sDall + wid * 2 * 32 * ST;
    uint* sPQ = sD + 32 * ST;

    int c = lane & 3;
    int r = lane >> 2;

    // kt 0-1 B-frags in registers
    const float* C = We1 + 2 * HID * HID;
    uint breg[2][8][2];
    #pragma unroll
    for (int kt = 0; kt < 2; kt++)
        #pragma unroll
        for (int nt = 0; nt < 8; nt++) {
            int n  = 8 * nt + r;
            int k0 = 16 * kt + 2 * c;
            int k1 = 16 * kt + 8 + 2 * c;
            __half2 h0 = __floats2half2_rn(C[k0 * HID + n], C[(k0 + 1) * HID + n]);
            __half2 h1 = __floats2half2_rn(C[k1 * HID + n], C[(k1 + 1) * HID + n]);
            breg[kt][nt][0] = *(uint*)&h0;
            breg[kt][nt][1] = *(uint*)&h1;
        }
    // kt 2-3 B-frags in block smem (each thread writes its own lane's frags)
    #pragma unroll
    for (int kt = 2; kt < 4; kt++)
        for (int nt = wid; nt < 8; nt += 4) {
            int n  = 8 * nt + r;
            int k0 = 16 * kt + 2 * c;
            int k1 = 16 * kt + 8 + 2 * c;
            __half2 h0 = __floats2half2_rn(C[k0 * HID + n], C[(k0 + 1) * HID + n]);
            __half2 h1 = __floats2half2_rn(C[k1 * HID + n], C[(k1 + 1) * HID + n]);
            sBf[(((kt - 2) * 8 + nt) * 32 + lane) * 2]     = *(uint*)&h0;
            sBf[(((kt - 2) * 8 + nt) * 32 + lane) * 2 + 1] = *(uint*)&h1;
        }
    if (tid < HID) sW2[tid] = We2[tid];
    __syncthreads();

    int txg = lane & 7;
    int tyg = lane >> 3;
    float bias = be2[0];
    int is64 = g_is64;
    uint sdbase  = smem_u32(sD);
    uint spqbase = smem_u32(sPQ);
    int n_wt = (n_edges + 31) >> 5;
    int stride = gridDim.x * 4;

    int t0 = blockIdx.x * 4 + wid;

    int2 myuv = make_int2(0, 0);
    if (t0 < n_wt) {
        long long eg = (long long)t0 * 32 + lane;
        if (eg >= n_edges) eg = n_edges - 1;
        if (is64) {
            int4 p4 = *(const int4*)&pairs[4 * eg];
            myuv = make_int2(p4.x, p4.z);
        } else {
            myuv = *(const int2*)&pairs[2 * eg];
        }
    }

    for (; t0 < n_wt; t0 += stride) {
        int ebase = t0 * 32;

        #pragma unroll
        for (int i = 0; i < 8; i++) {
            int e  = 8 * tyg + i;
            int u = __shfl_sync(0xffffffffu, myuv.x, e);
            int v = __shfl_sync(0xffffffffu, myuv.y, e);
            uint4 hu = *(const uint4*)&g_Hh[(size_t)u * HID + 8 * txg];
            uint4 hv = *(const uint4*)&g_Hh[(size_t)v * HID + 8 * txg];
            uint4 pu = *(const uint4*)&g_Ph[(size_t)u * HID + 8 * txg];
            uint4 qv = *(const uint4*)&g_Qh[(size_t)v * HID + 8 * txg];
            uint4 d, s;
            __half2 t;
            t = __habs2(__hsub2(*(__half2*)&hu.x, *(__half2*)&hv.x)); d.x = *(uint*)&t;
            t = __habs2(__hsub2(*(__half2*)&hu.y, *(__half2*)&hv.y)); d.y = *(uint*)&t;
            t = __habs2(__hsub2(*(__half2*)&hu.z, *(__half2*)&hv.z)); d.z = *(uint*)&t;
            t = __habs2(__hsub2(*(__half2*)&hu.w, *(__half2*)&hv.w)); d.w = *(uint*)&t;
            t = __hadd2(*(__half2*)&pu.x, *(__half2*)&qv.x); s.x = *(uint*)&t;
            t = __hadd2(*(__half2*)&pu.y, *(__half2*)&qv.y); s.y = *(uint*)&t;
            t = __hadd2(*(__half2*)&pu.z, *(__half2*)&qv.z); s.z = *(uint*)&t;
            t = __hadd2(*(__half2*)&pu.w, *(__half2*)&qv.w); s.w = *(uint*)&t;
            *(uint4*)&sD[e * ST + 4 * txg]  = d;
            *(uint4*)&sPQ[e * ST + 4 * txg] = s;
        }
        __syncwarp();

        // prefetch next tile's indices under the MMA
        {
            int tn = t0 + stride;
            if (tn < n_wt) {
                long long eg = (long long)tn * 32 + lane;
                if (eg >= n_edges) eg = n_edges - 1;
                if (is64) {
                    int4 p4 = *(const int4*)&pairs[4 * eg];
                    myuv = make_int2(p4.x, p4.z);
                } else {
                    myuv = *(const int2*)&pairs[2 * eg];
                }
            }
        }

        #pragma unroll
        for (int m = 0; m < 2; m++) {
            uint rowsel = ((16 * m + (lane & 15)) * ST + 4 * (lane >> 4)) << 2;
            float4 acc[8];
            #pragma unroll
            for (int nt = 0; nt < 8; nt++)
                acc[nt] = make_float4(0.f, 0.f, 0.f, 0.f);

            #pragma unroll
            for (int kt = 0; kt < 4; kt++) {
                uint a[4];
                ldm_x4(a, sdbase + rowsel + kt * 32);
                if (kt < 2) {
                    #pragma unroll
                    for (int nt = 0; nt < 8; nt++)
                        mma_f16(acc[nt], a, breg[kt][nt][0], breg[kt][nt][1]);
                } else {
                    #pragma unroll
                    for (int nt = 0; nt < 8; nt++) {
                        uint2 b = *(const uint2*)&sBf[(((kt - 2) * 8 + nt) * 32 + lane) * 2];
                        mma_f16(acc[nt], a, b.x, b.y);
                    }
                }
            }

            float sLo = 0.f, sHi = 0.f;
            #pragma unroll
            for (int kt = 0; kt < 4; kt++) {
                uint pq[4];
                ldm_x4(pq, spqbase + rowsel + kt * 32);
                #pragma unroll
                for (int h = 0; h < 2; h++) {
                    int nt = 2 * kt + h;
                    float w0 = sW2[8 * nt + 2 * c];
                    float w1 = sW2[8 * nt + 2 * c + 1];
                    float2 lo = __half22float2(*(__half2*)&pq[2 * h]);
                    float2 hi = __half22float2(*(__half2*)&pq[2 * h + 1]);
                    sLo = fmaf(fmaxf(acc[nt].x + lo.x, 0.f), w0, sLo);
                    sLo = fmaf(fmaxf(acc[nt].y + lo.y, 0.f), w1, sLo);
                    sHi = fmaf(fmaxf(acc[nt].z + hi.x, 0.f), w0, sHi);
                    sHi = fmaf(fmaxf(acc[nt].w + hi.y, 0.f), w1, sHi);
                }
            }
            sLo += __shfl_xor_sync(0xffffffffu, sLo, 1);
            sLo += __shfl_xor_sync(0xffffffffu, sLo, 2);
            sHi += __shfl_xor_sync(0xffffffffu, sHi, 1);
            sHi += __shfl_xor_sync(0xffffffffu, sHi, 2);
            if (c == 0) {
                int eLo = ebase + 16 * m + r;
                int eHi = eLo + 8;
                if (eLo < n_edges) out[eLo] = sLo + bias;
                if (eHi < n_edges) out[eHi] = sHi + bias;
            }
        }
        __syncwarp();
    }
}

// ---------------------------------------------------------------------------
extern "C" void kernel_launch(void* const* d_in, const int* in_sizes, int n_in,
                              void* d_out, int out_size) {
    const float* X     = (const float*)d_in[0];
    const int*   pairs = (const int*)d_in[1];
    const float* W1    = (const float*)d_in[2];
    const float* b1    = (const float*)d_in[3];
    const float* W2    = (const float*)d_in[4];
    const float* b2    = (const float*)d_in[5];
    const float* We1   = (const float*)d_in[6];
    const float* be1   = (const float*)d_in[7];
    const float* We2   = (const float*)d_in[8];
    const float* be2   = (const float*)d_in[9];
    float* out = (float*)d_out;

    int n_nodes = in_sizes[0] / 4;
    int n_edges = out_size;

    cudaFuncSetAttribute(node_kernel,
                         cudaFuncAttributeMaxDynamicSharedMemorySize, NODE_SMEM);
    cudaFuncSetAttribute(edge_kernel,
                         cudaFuncAttributeMaxDynamicSharedMemorySize, EDGE_SMEM);

    node_kernel<<<296, 256, NODE_SMEM>>>(X, W1, b1, W2, b2, We1, be1,
                                         n_nodes, pairs, n_edges);
    edge_kernel<<<740, 128, EDGE_SMEM>>>(pairs, We1, We2, be2, out, n_edges);
}

// round 17
// speedup vs baseline: 1.3705x; 1.3705x over previous
#include <cuda_runtime.h>
#include <cuda_fp16.h>

#define HID 64
#define MAX_NODES 100000
#define ST 36              // row stride in uints (ldmatrix conflict-free)
#define NODE_SMEM ((3 * 2048 + 128 * 36 + 128) * 4)
#define EDGE_SMEM ((64 + 4 * 2 * 32 * ST) * 4)

typedef unsigned int uint;

__device__ __half g_Hh[MAX_NODES * HID];
__device__ __half g_Ph[MAX_NODES * HID];
__device__ __half g_Qh[MAX_NODES * HID];

__device__ __forceinline__ void mma_f16(float4& d, const uint* a, uint b0, uint b1) {
    asm volatile(
        "mma.sync.aligned.m16n8k16.row.col.f32.f16.f16.f32 "
        "{%0,%1,%2,%3}, {%4,%5,%6,%7}, {%8,%9}, {%0,%1,%2,%3};"
        : "+f"(d.x), "+f"(d.y), "+f"(d.z), "+f"(d.w)
        : "r"(a[0]), "r"(a[1]), "r"(a[2]), "r"(a[3]), "r"(b0), "r"(b1));
}
__device__ __forceinline__ void ldm_x4(uint a[4], uint saddr) {
    asm volatile(
        "ldmatrix.sync.aligned.m8n8.x4.shared.b16 {%0,%1,%2,%3}, [%4];"
        : "=r"(a[0]), "=r"(a[1]), "=r"(a[2]), "=r"(a[3]) : "r"(saddr));
}
__device__ __forceinline__ uint smem_u32(const void* p) {
    return (uint)__cvta_generic_to_shared(p);
}

// ---------------------------------------------------------------------------
// Node kernel (v13/v14 structure). Signals PDL dependents at entry so edge
// blocks can begin their node-independent prologue concurrently.
// ---------------------------------------------------------------------------
__global__ __launch_bounds__(256, 2) void node_kernel(
        const float* __restrict__ X,
        const float* __restrict__ W1, const float* __restrict__ b1,
        const float* __restrict__ W2, const float* __restrict__ b2,
        const float* __restrict__ We1, const float* __restrict__ be1,
        int n_nodes) {
    asm volatile("griddepcontrol.launch_dependents;");

    extern __shared__ uint nsm[];
    uint*  sFr   = nsm;                     // [3][2048] frag-major W2, A, B
    uint*  sh    = nsm + 3 * 2048;          // [128][36] fp16 tile
    float* sbias = (float*)(nsm + 3 * 2048 + 128 * 36);

    int tid = threadIdx.x;

    for (int idx = tid; idx < 3 * 2048; idx += 256) {
        int arr = idx >> 11;
        int id  = idx & 2047;
        int which = id & 1;
        int ln    = (id >> 1) & 31;
        int nt    = (id >> 6) & 7;
        int kt    = id >> 9;
        int cc = ln & 3;
        int rr = ln >> 2;
        int k0 = 16 * kt + (which ? 8 : 0) + 2 * cc;
        int n  = 8 * nt + rr;
        const float* W = (arr == 0) ? W2 : (We1 + (size_t)(arr - 1) * 4096);
        __half2 h = __floats2half2_rn(W[k0 * HID + n], W[(k0 + 1) * HID + n]);
        sFr[idx] = *(uint*)&h;
    }
    if (tid < 64)  sbias[tid] = b2[tid];
    else if (tid < 128) sbias[tid] = be1[tid - 64];

    int q = tid & 15;
    int g = tid >> 4;
    int lane = tid & 31;
    int w    = tid >> 5;
    int c = lane & 3;
    int r = lane >> 2;

    float w1r[4][4];
    #pragma unroll
    for (int cc = 0; cc < 4; cc++) {
        float4 wv = *(const float4*)&W1[cc * HID + 4 * q];
        w1r[cc][0] = wv.x; w1r[cc][1] = wv.y; w1r[cc][2] = wv.z; w1r[cc][3] = wv.w;
    }
    float4 b1r = *(const float4*)&b1[4 * q];

    uint* sW2f = sFr;
    uint* sAf  = sFr + 2048;
    uint* sBf  = sFr + 4096;
    uint shbase = smem_u32(sh);
    uint aaddr0 = shbase + (((16 * w + (lane & 15)) * ST + 4 * (lane >> 4)) << 2);
    __syncthreads();

    for (int tb = blockIdx.x * 128; tb < n_nodes; tb += gridDim.x * 128) {
        #pragma unroll
        for (int i = 0; i < 8; i++) {
            int node = tb + 8 * g + i;
            float4 x = (node < n_nodes) ? *(const float4*)&X[(size_t)node * 4]
                                        : make_float4(0.f, 0.f, 0.f, 0.f);
            float h[4];
            #pragma unroll
            for (int m = 0; m < 4; m++) {
                float hh = ((const float*)&b1r)[m];
                hh = fmaf(x.x, w1r[0][m], hh);
                hh = fmaf(x.y, w1r[1][m], hh);
                hh = fmaf(x.z, w1r[2][m], hh);
                hh = fmaf(x.w, w1r[3][m], hh);
                h[m] = fmaxf(hh, 0.f);
            }
            __half2 h01 = __floats2half2_rn(h[0], h[1]);
            __half2 h23 = __floats2half2_rn(h[2], h[3]);
            *(uint2*)&sh[(8 * g + i) * ST + 2 * q] =
                make_uint2(*(uint*)&h01, *(uint*)&h23);
        }
        __syncwarp();

        {
            float4 acc[8];
            #pragma unroll
            for (int nt = 0; nt < 8; nt++) acc[nt] = make_float4(0.f, 0.f, 0.f, 0.f);
            #pragma unroll
            for (int kt = 0; kt < 4; kt++) {
                uint a[4];
                ldm_x4(a, aaddr0 + kt * 32);
                #pragma unroll
                for (int nt = 0; nt < 8; nt++) {
                    uint2 b = *(const uint2*)&sW2f[((kt * 8 + nt) * 32 + lane) * 2];
                    mma_f16(acc[nt], a, b.x, b.y);
                }
            }
            __syncwarp();
            #pragma unroll
            for (int nt = 0; nt < 8; nt++) {
                float2 bv = *(const float2*)&sbias[8 * nt + 2 * c];
                __half2 lo = __floats2half2_rn(fmaxf(acc[nt].x + bv.x, 0.f),
                                               fmaxf(acc[nt].y + bv.y, 0.f));
                __half2 hi = __floats2half2_rn(fmaxf(acc[nt].z + bv.x, 0.f),
                                               fmaxf(acc[nt].w + bv.y, 0.f));
                sh[(16 * w + r) * ST + 4 * nt + c]     = *(uint*)&lo;
                sh[(16 * w + 8 + r) * ST + 4 * nt + c] = *(uint*)&hi;
            }
        }
        __syncwarp();

        {
            float4 pA[8], qA[8];
            #pragma unroll
            for (int nt = 0; nt < 8; nt++) {
                pA[nt] = make_float4(0.f, 0.f, 0.f, 0.f);
                qA[nt] = make_float4(0.f, 0.f, 0.f, 0.f);
            }
            #pragma unroll
            for (int kt = 0; kt < 4; kt++) {
                uint a[4];
                ldm_x4(a, aaddr0 + kt * 32);
                #pragma unroll
                for (int nt = 0; nt < 8; nt++) {
                    uint2 ba = *(const uint2*)&sAf[((kt * 8 + nt) * 32 + lane) * 2];
                    uint2 bb = *(const uint2*)&sBf[((kt * 8 + nt) * 32 + lane) * 2];
                    mma_f16(pA[nt], a, ba.x, ba.y);
                    mma_f16(qA[nt], a, bb.x, bb.y);
                }
            }
            int nodeLo = tb + 16 * w + r;
            int nodeHi = nodeLo + 8;
            #pragma unroll
            for (int nt = 0; nt < 8; nt++) {
                float2 be = *(const float2*)&sbias[64 + 8 * nt + 2 * c];
                if (nodeLo < n_nodes) {
                    __half2 p = __floats2half2_rn(pA[nt].x + be.x, pA[nt].y + be.y);
                    __half2 qq = __floats2half2_rn(qA[nt].x, qA[nt].y);
                    *(uint*)&g_Ph[(size_t)nodeLo * HID + 8 * nt + 2 * c] = *(uint*)&p;
                    *(uint*)&g_Qh[(size_t)nodeLo * HID + 8 * nt + 2 * c] = *(uint*)&qq;
                }
                if (nodeHi < n_nodes) {
                    __half2 p = __floats2half2_rn(pA[nt].z + be.x, pA[nt].w + be.y);
                    __half2 qq = __floats2half2_rn(qA[nt].z, qA[nt].w);
                    *(uint*)&g_Ph[(size_t)nodeHi * HID + 8 * nt + 2 * c] = *(uint*)&p;
                    *(uint*)&g_Qh[(size_t)nodeHi * HID + 8 * nt + 2 * c] = *(uint*)&qq;
                }
            }
        }

        #pragma unroll
        for (int it = 0; it < 4; it++) {
            int id2 = it * 32 + lane;
            int row = id2 >> 3, ch = id2 & 7;
            int node = tb + 16 * w + row;
            if (node < n_nodes)
                *(uint4*)&g_Hh[(size_t)node * HID + ch * 8] =
                    *(const uint4*)&sh[(16 * w + row) * ST + ch * 4];
        }
        __syncwarp();
    }
}

// ---------------------------------------------------------------------------
// Edge kernel v17 (= v14 + PDL): node-independent prologue (per-block dtype
// detection from pairs, B-frags, sW2, first index prefetch), then
// griddepcontrol.wait before the first gather of node output.
// ---------------------------------------------------------------------------
__global__ __launch_bounds__(128, 4) void edge_kernel(
        const int* __restrict__ pairs,
        const float* __restrict__ We1,
        const float* __restrict__ We2,
        const float* __restrict__ be2,
        float* __restrict__ out,
        int n_edges) {
    extern __shared__ uint es17[];
    float* sW2 = (float*)es17;               // [64]
    uint*  sDall = es17 + 64;                // 4 warps x (sD[32][ST], sPQ[32][ST])

    int tid  = threadIdx.x;
    int lane = tid & 31;
    int wid  = tid >> 5;
    uint* sD  = sDall + wid * 2 * 32 * ST;
    uint* sPQ = sD + 32 * ST;

    int c = lane & 3;
    int r = lane >> 2;

    // ---- per-block dtype detection (reads only pairs; PDL-safe) ----
    int nz = 0;
    {
        long long idx = 1 + 2 * ((long long)tid * (n_edges - 1) / 128);
        if (idx < 2LL * n_edges) nz = pairs[idx];
    }
    int is64 = (__syncthreads_or(nz) == 0) ? 1 : 0;

    // B(C) fragments in registers, loaded once (weights: inputs, PDL-safe).
    const float* C = We1 + 2 * HID * HID;
    uint breg[4][8][2];
    #pragma unroll
    for (int kt = 0; kt < 4; kt++)
        #pragma unroll
        for (int nt = 0; nt < 8; nt++) {
            int n  = 8 * nt + r;
            int k0 = 16 * kt + 2 * c;
            int k1 = 16 * kt + 8 + 2 * c;
            __half2 h0 = __floats2half2_rn(C[k0 * HID + n], C[(k0 + 1) * HID + n]);
            __half2 h1 = __floats2half2_rn(C[k1 * HID + n], C[(k1 + 1) * HID + n]);
            breg[kt][nt][0] = *(uint*)&h0;
            breg[kt][nt][1] = *(uint*)&h1;
        }
    if (tid < HID) sW2[tid] = We2[tid];
    float bias = be2[0];

    int n_wt = (n_edges + 31) >> 5;
    int stride = gridDim.x * 4;
    int t0 = blockIdx.x * 4 + wid;

    // first-tile index prefetch (reads only pairs; PDL-safe)
    int2 myuv = make_int2(0, 0);
    if (t0 < n_wt) {
        long long eg = (long long)t0 * 32 + lane;
        if (eg >= n_edges) eg = n_edges - 1;
        if (is64) {
            int4 p4 = *(const int4*)&pairs[4 * eg];
            myuv = make_int2(p4.x, p4.z);
        } else {
            myuv = *(const int2*)&pairs[2 * eg];
        }
    }
    __syncthreads();

    // ---- PDL barrier: node grid's writes visible after this ----
    asm volatile("griddepcontrol.wait;");

    int txg = lane & 7;
    int tyg = lane >> 3;
    uint sdbase  = smem_u32(sD);
    uint spqbase = smem_u32(sPQ);

    for (; t0 < n_wt; t0 += stride) {
        int ebase = t0 * 32;

        #pragma unroll
        for (int i = 0; i < 8; i++) {
            int e = 8 * tyg + i;
            int u = __shfl_sync(0xffffffffu, myuv.x, e);
            int v = __shfl_sync(0xffffffffu, myuv.y, e);
            uint4 hu = *(const uint4*)&g_Hh[(size_t)u * HID + 8 * txg];
            uint4 hv = *(const uint4*)&g_Hh[(size_t)v * HID + 8 * txg];
            uint4 pu = *(const uint4*)&g_Ph[(size_t)u * HID + 8 * txg];
            uint4 qv = *(const uint4*)&g_Qh[(size_t)v * HID + 8 * txg];
            uint4 d, s;
            __half2 t;
            t = __habs2(__hsub2(*(__half2*)&hu.x, *(__half2*)&hv.x)); d.x = *(uint*)&t;
            t = __habs2(__hsub2(*(__half2*)&hu.y, *(__half2*)&hv.y)); d.y = *(uint*)&t;
            t = __habs2(__hsub2(*(__half2*)&hu.z, *(__half2*)&hv.z)); d.z = *(uint*)&t;
            t = __habs2(__hsub2(*(__half2*)&hu.w, *(__half2*)&hv.w)); d.w = *(uint*)&t;
            t = __hadd2(*(__half2*)&pu.x, *(__half2*)&qv.x); s.x = *(uint*)&t;
            t = __hadd2(*(__half2*)&pu.y, *(__half2*)&qv.y); s.y = *(uint*)&t;
            t = __hadd2(*(__half2*)&pu.z, *(__half2*)&qv.z); s.z = *(uint*)&t;
            t = __hadd2(*(__half2*)&pu.w, *(__half2*)&qv.w); s.w = *(uint*)&t;
            *(uint4*)&sD[e * ST + 4 * txg]  = d;
            *(uint4*)&sPQ[e * ST + 4 * txg] = s;
        }
        __syncwarp();

        // prefetch next tile's indices under the MMA
        {
            int tn = t0 + stride;
            if (tn < n_wt) {
                long long eg = (long long)tn * 32 + lane;
                if (eg >= n_edges) eg = n_edges - 1;
                if (is64) {
                    int4 p4 = *(const int4*)&pairs[4 * eg];
                    myuv = make_int2(p4.x, p4.z);
                } else {
                    myuv = *(const int2*)&pairs[2 * eg];
                }
            }
        }

        #pragma unroll
        for (int m = 0; m < 2; m++) {
            uint rowsel = ((16 * m + (lane & 15)) * ST + 4 * (lane >> 4)) << 2;
            float4 acc[8];
            #pragma unroll
            for (int nt = 0; nt < 8; nt++)
                acc[nt] = make_float4(0.f, 0.f, 0.f, 0.f);

            #pragma unroll
            for (int kt = 0; kt < 4; kt++) {
                uint a[4];
                ldm_x4(a, sdbase + rowsel + kt * 32);
                #pragma unroll
                for (int nt = 0; nt < 8; nt++)
                    mma_f16(acc[nt], a, breg[kt][nt][0], breg[kt][nt][1]);
            }

            float sLo = 0.f, sHi = 0.f;
            #pragma unroll
            for (int kt = 0; kt < 4; kt++) {
                uint pq[4];
                ldm_x4(pq, spqbase + rowsel + kt * 32);
                #pragma unroll
                for (int h = 0; h < 2; h++) {
                    int nt = 2 * kt + h;
                    float w0 = sW2[8 * nt + 2 * c];
                    float w1 = sW2[8 * nt + 2 * c + 1];
                    float2 lo = __half22float2(*(__half2*)&pq[2 * h]);
                    float2 hi = __half22float2(*(__half2*)&pq[2 * h + 1]);
                    sLo = fmaf(fmaxf(acc[nt].x + lo.x, 0.f), w0, sLo);
                    sLo = fmaf(fmaxf(acc[nt].y + lo.y, 0.f), w1, sLo);
                    sHi = fmaf(fmaxf(acc[nt].z + hi.x, 0.f), w0, sHi);
                    sHi = fmaf(fmaxf(acc[nt].w + hi.y, 0.f), w1, sHi);
                }
            }
            sLo += __shfl_xor_sync(0xffffffffu, sLo, 1);
            sLo += __shfl_xor_sync(0xffffffffu, sLo, 2);
            sHi += __shfl_xor_sync(0xffffffffu, sHi, 1);
            sHi += __shfl_xor_sync(0xffffffffu, sHi, 2);
            if (c == 0) {
                int eLo = ebase + 16 * m + r;
                int eHi = eLo + 8;
                if (eLo < n_edges) out[eLo] = sLo + bias;
                if (eHi < n_edges) out[eHi] = sHi + bias;
            }
        }
        __syncwarp();
    }
}

// ---------------------------------------------------------------------------
extern "C" void kernel_launch(void* const* d_in, const int* in_sizes, int n_in,
                              void* d_out, int out_size) {
    const float* X     = (const float*)d_in[0];
    const int*   pairs = (const int*)d_in[1];
    const float* W1    = (const float*)d_in[2];
    const float* b1    = (const float*)d_in[3];
    const float* W2    = (const float*)d_in[4];
    const float* b2    = (const float*)d_in[5];
    const float* We1   = (const float*)d_in[6];
    const float* be1   = (const float*)d_in[7];
    const float* We2   = (const float*)d_in[8];
    const float* be2   = (const float*)d_in[9];
    float* out = (float*)d_out;

    int n_nodes = in_sizes[0] / 4;
    int n_edges = out_size;

    cudaFuncSetAttribute(node_kernel,
                         cudaFuncAttributeMaxDynamicSharedMemorySize, NODE_SMEM);
    cudaFuncSetAttribute(edge_kernel,
                         cudaFuncAttributeMaxDynamicSharedMemorySize, EDGE_SMEM);

    node_kernel<<<296, 256, NODE_SMEM>>>(X, W1, b1, W2, b2, We1, be1, n_nodes);

    // Edge launch with programmatic dependent launch; fall back to a plain
    // launch if the attribute is unsupported in this capture context.
    cudaLaunchConfig_t cfg = {};
    cfg.gridDim  = dim3(592, 1, 1);
    cfg.blockDim = dim3(128, 1, 1);
    cfg.dynamicSmemBytes = EDGE_SMEM;
    cudaLaunchAttribute attrs[1];
    attrs[0].id = cudaLaunchAttributeProgrammaticStreamSerialization;
    attrs[0].val.programmaticStreamSerializationAllowed = 1;
    cfg.attrs = attrs;
    cfg.numAttrs = 1;
    cudaError_t err = cudaLaunchKernelEx(&cfg, edge_kernel,
                                         pairs, We1, We2, be2, out, n_edges);
    if (err != cudaSuccess) {
        cudaGetLastError();   // clear
        edge_kernel<<<592, 128, EDGE_SMEM>>>(pairs, We1, We2, be2, out, n_edges);
    }
}